// round 5
// baseline (speedup 1.0000x reference)
#include <cuda_runtime.h>

// ---------------------------------------------------------------------------
// GCN layer (push-mode segment mean + tiny per-node MLPs)
// R5: R4 with legal PTX for L2 eviction hint (createpolicy + cache_hint).
// ---------------------------------------------------------------------------

#define NODE_CAP 1048576  // N = 1e6 in this problem

// Scratch: xyz = neighbor-feature sum, w = degree
__device__ float4 g_accum[NODE_CAP];
// Repacked features: xyz = feature, w = 1.0
__device__ float4 g_feat[NODE_CAP];

// ---------------- prep: zero accum + pack feature(+1.0), 4 nodes/thread ----
__global__ void prep_kernel(const float4* __restrict__ feat4, int n) {
    int t = blockIdx.x * blockDim.x + threadIdx.x;
    int i0 = t * 4;
    if (i0 + 3 < n) {
        float4 a = feat4[3 * t];      // f[0].xyz f[1].x
        float4 b = feat4[3 * t + 1];  // f[1].yz  f[2].xy
        float4 c = feat4[3 * t + 2];  // f[2].z   f[3].xyz
        g_feat[i0 + 0] = make_float4(a.x, a.y, a.z, 1.0f);
        g_feat[i0 + 1] = make_float4(a.w, b.x, b.y, 1.0f);
        g_feat[i0 + 2] = make_float4(b.z, b.w, c.x, 1.0f);
        g_feat[i0 + 3] = make_float4(c.y, c.z, c.w, 1.0f);
        float4 z = make_float4(0.f, 0.f, 0.f, 0.f);
        g_accum[i0 + 0] = z; g_accum[i0 + 1] = z;
        g_accum[i0 + 2] = z; g_accum[i0 + 3] = z;
    } else if (i0 < n) {
        const float* f = (const float*)feat4;
        for (int k = i0; k < n; k++) {
            g_feat[k] = make_float4(f[3 * k], f[3 * k + 1], f[3 * k + 2], 1.0f);
            g_accum[k] = make_float4(0.f, 0.f, 0.f, 0.f);
        }
    }
}

// ---------------- edge phase ------------------------------------------------
__device__ __forceinline__ void edge_op(int s, int d, unsigned long long pol) {
    float a, b, c, w;
    // keep the feature table L2-resident (evict_last policy), L1-bypass (nc)
    asm volatile("ld.global.nc.L2::cache_hint.v4.f32 {%0,%1,%2,%3}, [%4], %5;"
                 : "=f"(a), "=f"(b), "=f"(c), "=f"(w)
                 : "l"(g_feat + s), "l"(pol));
    float4* p = g_accum + d;
    asm volatile("red.global.add.v4.f32 [%0], {%1, %2, %3, %4};"
                 :: "l"(p), "f"(a), "f"(b), "f"(c), "f"(w) : "memory");
}

__global__ void edge_kernel(const int* __restrict__ src,
                            const int* __restrict__ dst,
                            int e8, int rem) {
    unsigned long long pol;
    asm("createpolicy.fractional.L2::evict_last.b64 %0, 1.0;" : "=l"(pol));
    int i = blockIdx.x * blockDim.x + threadIdx.x;
    if (i < e8) {
        const int4* s4 = reinterpret_cast<const int4*>(src) + i * 2;
        const int4* d4 = reinterpret_cast<const int4*>(dst) + i * 2;
        int4 sA = __ldcs(s4);     int4 dA = __ldcs(d4);      // evict-first stream
        int4 sB = __ldcs(s4 + 1); int4 dB = __ldcs(d4 + 1);
        edge_op(sA.x, dA.x, pol); edge_op(sA.y, dA.y, pol);
        edge_op(sA.z, dA.z, pol); edge_op(sA.w, dA.w, pol);
        edge_op(sB.x, dB.x, pol); edge_op(sB.y, dB.y, pol);
        edge_op(sB.z, dB.z, pol); edge_op(sB.w, dB.w, pol);
    } else if (i == e8 && rem) {
        int base = e8 * 8;
        for (int k = 0; k < rem; k++)
            edge_op(src[base + k], dst[base + k], pol);
    }
}

// ---------------- node phase: 4 nodes/thread, fully vectorized --------------
__global__ void node_kernel(const float4* __restrict__ x_attr4,
                            const float4* __restrict__ label4,
                            const float* __restrict__ W0, const float* __restrict__ b0,
                            const float* __restrict__ W1, const float* __restrict__ b1,
                            const float* __restrict__ W2, const float* __restrict__ b2,
                            const float* __restrict__ Wa, const float* __restrict__ ba,
                            float4* __restrict__ out4, int n) {
    __shared__ float sW0[3], sW1[9], sW2[6], sWa[27], sB[3], sBa[3];
    int t = threadIdx.x;
    if (t < 3)  { sW0[t] = W0[t]; sB[t] = b0[t] + b1[t] + b2[t]; sBa[t] = ba[t]; }
    if (t < 9)  sW1[t] = W1[t];
    if (t < 6)  sW2[t] = W2[t];
    if (t < 27) sWa[t] = Wa[t];
    __syncthreads();

    int tid = blockIdx.x * blockDim.x + threadIdx.x;
    int i0 = tid * 4;
    if (i0 >= n) return;

    float o[12];

    if (i0 + 3 < n) {
        float4 xa = x_attr4[2 * tid];
        float4 xb = x_attr4[2 * tid + 1];
        float4 lb4 = label4[tid];
        float xs[8] = {xa.x, xa.y, xa.z, xa.w, xb.x, xb.y, xb.z, xb.w};
        float ls[4] = {lb4.x, lb4.y, lb4.z, lb4.w};

#pragma unroll
        for (int k = 0; k < 4; k++) {
            int i = i0 + k;
            float4 acc = g_accum[i];
            float inv = 1.0f / fmaxf(acc.w, 1.0f);
            float hg0 = acc.x * inv, hg1 = acc.y * inv, hg2 = acc.z * inv;
            float4 f4 = g_feat[i];
            float x0 = xs[2 * k], x1 = xs[2 * k + 1];
            float lb = ls[k];

            float a[3];
#pragma unroll
            for (int j = 0; j < 3; j++) {
                float v = lb * sW0[j]
                        + hg0 * sW1[j] + hg1 * sW1[3 + j] + hg2 * sW1[6 + j]
                        + x0 * sW2[j] + x1 * sW2[3 + j]
                        + sB[j];
                a[j] = fmaxf(v, 0.f);
            }
#pragma unroll
            for (int j = 0; j < 3; j++) {
                float v = a[0] * sWa[j] + a[1] * sWa[3 + j] + a[2] * sWa[6 + j]
                        + hg0 * sWa[9 + j] + hg1 * sWa[12 + j] + hg2 * sWa[15 + j]
                        + f4.x * sWa[18 + j] + f4.y * sWa[21 + j] + f4.z * sWa[24 + j]
                        + sBa[j];
                o[3 * k + j] = fmaxf(v, 0.f);
            }
        }
        out4[3 * tid]     = make_float4(o[0], o[1], o[2], o[3]);
        out4[3 * tid + 1] = make_float4(o[4], o[5], o[6], o[7]);
        out4[3 * tid + 2] = make_float4(o[8], o[9], o[10], o[11]);
    } else {
        // scalar tail
        const float* x_attr = (const float*)x_attr4;
        const float* label  = (const float*)label4;
        float* out = (float*)out4;
        for (int i = i0; i < n; i++) {
            float4 acc = g_accum[i];
            float inv = 1.0f / fmaxf(acc.w, 1.0f);
            float hg0 = acc.x * inv, hg1 = acc.y * inv, hg2 = acc.z * inv;
            float4 f4 = g_feat[i];
            float x0 = x_attr[2 * i], x1 = x_attr[2 * i + 1];
            float lb = label[i];
            float a[3];
            for (int j = 0; j < 3; j++) {
                float v = lb * sW0[j]
                        + hg0 * sW1[j] + hg1 * sW1[3 + j] + hg2 * sW1[6 + j]
                        + x0 * sW2[j] + x1 * sW2[3 + j] + sB[j];
                a[j] = fmaxf(v, 0.f);
            }
            for (int j = 0; j < 3; j++) {
                float v = a[0] * sWa[j] + a[1] * sWa[3 + j] + a[2] * sWa[6 + j]
                        + hg0 * sWa[9 + j] + hg1 * sWa[12 + j] + hg2 * sWa[15 + j]
                        + f4.x * sWa[18 + j] + f4.y * sWa[21 + j] + f4.z * sWa[24 + j]
                        + sBa[j];
                out[3 * i + j] = fmaxf(v, 0.f);
            }
        }
    }
}

extern "C" void kernel_launch(void* const* d_in, const int* in_sizes, int n_in,
                              void* d_out, int out_size) {
    const float* feature = (const float*)d_in[0];
    const float* x_attr  = (const float*)d_in[1];
    const float* label   = (const float*)d_in[2];
    const float* W0 = (const float*)d_in[3];
    const float* b0 = (const float*)d_in[4];
    const float* W1 = (const float*)d_in[5];
    const float* b1 = (const float*)d_in[6];
    const float* W2 = (const float*)d_in[7];
    const float* b2 = (const float*)d_in[8];
    const float* Wa = (const float*)d_in[9];
    const float* ba = (const float*)d_in[10];
    const int*   src = (const int*)d_in[11];
    const int*   dst = (const int*)d_in[12];

    int N = in_sizes[0] / 3;
    int E = in_sizes[11];
    int e8 = E / 8;
    int rem = E % 8;

    const int TB = 256;
    int prep_thr = (N + 3) / 4;
    prep_kernel<<<(prep_thr + TB - 1) / TB, TB>>>((const float4*)feature, N);

    int edge_thr = e8 + (rem ? 1 : 0);
    edge_kernel<<<(edge_thr + TB - 1) / TB, TB>>>(src, dst, e8, rem);

    int node_thr = (N + 3) / 4;
    node_kernel<<<(node_thr + TB - 1) / TB, TB>>>(
        (const float4*)x_attr, (const float4*)label,
        W0, b0, W1, b1, W2, b2, Wa, ba,
        (float4*)d_out, N);
}

// round 6
// speedup vs baseline: 1.0517x; 1.0517x over previous
#include <cuda_runtime.h>

// ---------------------------------------------------------------------------
// GCN layer (push-mode segment mean + tiny per-node MLPs)
// R6: revert R5's cache-policy + vec-prep regressions to the R2 edge/prep
//     config; keep the 4-node vectorized node kernel.
// ---------------------------------------------------------------------------

#define NODE_CAP 1048576  // N = 1e6 in this problem

// Scratch: xyz = neighbor-feature sum, w = degree
__device__ float4 g_accum[NODE_CAP];
// Repacked features: xyz = feature, w = 1.0
__device__ float4 g_feat[NODE_CAP];

// ---------------- prep: zero accum + pack feature(+1.0), 1 node/thread -----
__global__ void prep_kernel(const float* __restrict__ feat, int n) {
    int i = blockIdx.x * blockDim.x + threadIdx.x;
    if (i < n) {
        g_accum[i] = make_float4(0.f, 0.f, 0.f, 0.f);
        g_feat[i]  = make_float4(feat[3 * i], feat[3 * i + 1], feat[3 * i + 2], 1.0f);
    }
}

// ---------------- edge phase ------------------------------------------------
__device__ __forceinline__ void edge_op(int s, int d) {
    float4 f = __ldg(&g_feat[s]);
    float4* p = g_accum + d;
    asm volatile("red.global.add.v4.f32 [%0], {%1, %2, %3, %4};"
                 :: "l"(p), "f"(f.x), "f"(f.y), "f"(f.z), "f"(f.w) : "memory");
}

__global__ void edge_kernel(const int* __restrict__ src,
                            const int* __restrict__ dst,
                            int e4, int rem) {
    int i = blockIdx.x * blockDim.x + threadIdx.x;
    if (i < e4) {
        int4 s = reinterpret_cast<const int4*>(src)[i];
        int4 d = reinterpret_cast<const int4*>(dst)[i];
        edge_op(s.x, d.x);
        edge_op(s.y, d.y);
        edge_op(s.z, d.z);
        edge_op(s.w, d.w);
    } else if (i == e4 && rem) {
        int base = e4 * 4;
        for (int k = 0; k < rem; k++)
            edge_op(src[base + k], dst[base + k]);
    }
}

// ---------------- node phase: 4 nodes/thread, fully vectorized --------------
__global__ void node_kernel(const float4* __restrict__ x_attr4,
                            const float4* __restrict__ label4,
                            const float* __restrict__ W0, const float* __restrict__ b0,
                            const float* __restrict__ W1, const float* __restrict__ b1,
                            const float* __restrict__ W2, const float* __restrict__ b2,
                            const float* __restrict__ Wa, const float* __restrict__ ba,
                            float4* __restrict__ out4, int n) {
    __shared__ float sW0[3], sW1[9], sW2[6], sWa[27], sB[3], sBa[3];
    int t = threadIdx.x;
    if (t < 3)  { sW0[t] = W0[t]; sB[t] = b0[t] + b1[t] + b2[t]; sBa[t] = ba[t]; }
    if (t < 9)  sW1[t] = W1[t];
    if (t < 6)  sW2[t] = W2[t];
    if (t < 27) sWa[t] = Wa[t];
    __syncthreads();

    int tid = blockIdx.x * blockDim.x + threadIdx.x;
    int i0 = tid * 4;
    if (i0 >= n) return;

    float o[12];

    if (i0 + 3 < n) {
        float4 xa = x_attr4[2 * tid];
        float4 xb = x_attr4[2 * tid + 1];
        float4 lb4 = label4[tid];
        float xs[8] = {xa.x, xa.y, xa.z, xa.w, xb.x, xb.y, xb.z, xb.w};
        float ls[4] = {lb4.x, lb4.y, lb4.z, lb4.w};

#pragma unroll
        for (int k = 0; k < 4; k++) {
            int i = i0 + k;
            float4 acc = g_accum[i];
            float inv = 1.0f / fmaxf(acc.w, 1.0f);
            float hg0 = acc.x * inv, hg1 = acc.y * inv, hg2 = acc.z * inv;
            float4 f4 = g_feat[i];
            float x0 = xs[2 * k], x1 = xs[2 * k + 1];
            float lb = ls[k];

            float a[3];
#pragma unroll
            for (int j = 0; j < 3; j++) {
                float v = lb * sW0[j]
                        + hg0 * sW1[j] + hg1 * sW1[3 + j] + hg2 * sW1[6 + j]
                        + x0 * sW2[j] + x1 * sW2[3 + j]
                        + sB[j];
                a[j] = fmaxf(v, 0.f);
            }
#pragma unroll
            for (int j = 0; j < 3; j++) {
                float v = a[0] * sWa[j] + a[1] * sWa[3 + j] + a[2] * sWa[6 + j]
                        + hg0 * sWa[9 + j] + hg1 * sWa[12 + j] + hg2 * sWa[15 + j]
                        + f4.x * sWa[18 + j] + f4.y * sWa[21 + j] + f4.z * sWa[24 + j]
                        + sBa[j];
                o[3 * k + j] = fmaxf(v, 0.f);
            }
        }
        out4[3 * tid]     = make_float4(o[0], o[1], o[2], o[3]);
        out4[3 * tid + 1] = make_float4(o[4], o[5], o[6], o[7]);
        out4[3 * tid + 2] = make_float4(o[8], o[9], o[10], o[11]);
    } else {
        // scalar tail
        const float* x_attr = (const float*)x_attr4;
        const float* label  = (const float*)label4;
        float* out = (float*)out4;
        for (int i = i0; i < n; i++) {
            float4 acc = g_accum[i];
            float inv = 1.0f / fmaxf(acc.w, 1.0f);
            float hg0 = acc.x * inv, hg1 = acc.y * inv, hg2 = acc.z * inv;
            float4 f4 = g_feat[i];
            float x0 = x_attr[2 * i], x1 = x_attr[2 * i + 1];
            float lb = label[i];
            float a[3];
            for (int j = 0; j < 3; j++) {
                float v = lb * sW0[j]
                        + hg0 * sW1[j] + hg1 * sW1[3 + j] + hg2 * sW1[6 + j]
                        + x0 * sW2[j] + x1 * sW2[3 + j] + sB[j];
                a[j] = fmaxf(v, 0.f);
            }
            for (int j = 0; j < 3; j++) {
                float v = a[0] * sWa[j] + a[1] * sWa[3 + j] + a[2] * sWa[6 + j]
                        + hg0 * sWa[9 + j] + hg1 * sWa[12 + j] + hg2 * sWa[15 + j]
                        + f4.x * sWa[18 + j] + f4.y * sWa[21 + j] + f4.z * sWa[24 + j]
                        + sBa[j];
                out[3 * i + j] = fmaxf(v, 0.f);
            }
        }
    }
}

extern "C" void kernel_launch(void* const* d_in, const int* in_sizes, int n_in,
                              void* d_out, int out_size) {
    const float* feature = (const float*)d_in[0];
    const float* x_attr  = (const float*)d_in[1];
    const float* label   = (const float*)d_in[2];
    const float* W0 = (const float*)d_in[3];
    const float* b0 = (const float*)d_in[4];
    const float* W1 = (const float*)d_in[5];
    const float* b1 = (const float*)d_in[6];
    const float* W2 = (const float*)d_in[7];
    const float* b2 = (const float*)d_in[8];
    const float* Wa = (const float*)d_in[9];
    const float* ba = (const float*)d_in[10];
    const int*   src = (const int*)d_in[11];
    const int*   dst = (const int*)d_in[12];

    int N = in_sizes[0] / 3;
    int E = in_sizes[11];
    int e4 = E / 4;
    int rem = E % 4;

    const int TB = 256;
    prep_kernel<<<(N + TB - 1) / TB, TB>>>(feature, N);

    int edge_thr = e4 + (rem ? 1 : 0);
    edge_kernel<<<(edge_thr + TB - 1) / TB, TB>>>(src, dst, e4, rem);

    int node_thr = (N + 3) / 4;
    node_kernel<<<(node_thr + TB - 1) / TB, TB>>>(
        (const float4*)x_attr, (const float4*)label,
        W0, b0, W1, b1, W2, b2, Wa, ba,
        (float4*)d_out, N);
}

// round 7
// speedup vs baseline: 1.0815x; 1.0283x over previous
#include <cuda_runtime.h>

// ---------------------------------------------------------------------------
// GCN layer (push-mode segment mean + tiny per-node MLPs)
// R7: R2 base (scalar prep + scalar node kernel) with edge phase restructured
//     for MLP: batch 4 gathers into registers, then 4 REDG.v4 (no "memory"
//     clobber between gathers). prep_kernel duration = clock canary.
// ---------------------------------------------------------------------------

#define NODE_CAP 1048576  // N = 1e6 in this problem

// Scratch: xyz = neighbor-feature sum, w = degree
__device__ float4 g_accum[NODE_CAP];
// Repacked features: xyz = feature, w = 1.0
__device__ float4 g_feat[NODE_CAP];

// ---------------- prep: zero accum + pack feature(+1.0), 1 node/thread -----
__global__ void prep_kernel(const float* __restrict__ feat, int n) {
    int i = blockIdx.x * blockDim.x + threadIdx.x;
    if (i < n) {
        g_accum[i] = make_float4(0.f, 0.f, 0.f, 0.f);
        g_feat[i]  = make_float4(feat[3 * i], feat[3 * i + 1], feat[3 * i + 2], 1.0f);
    }
}

// ---------------- edge phase ------------------------------------------------
__device__ __forceinline__ void red_v4(int d, float4 f) {
    float4* p = g_accum + d;
    // volatile keeps the op; no "memory" clobber so independent gathers can
    // be scheduled above/between the reductions.
    asm volatile("red.global.add.v4.f32 [%0], {%1, %2, %3, %4};"
                 :: "l"(p), "f"(f.x), "f"(f.y), "f"(f.z), "f"(f.w));
}

__global__ void edge_kernel(const int* __restrict__ src,
                            const int* __restrict__ dst,
                            int e4, int rem) {
    int i = blockIdx.x * blockDim.x + threadIdx.x;
    if (i < e4) {
        int4 s = reinterpret_cast<const int4*>(src)[i];
        int4 d = reinterpret_cast<const int4*>(dst)[i];
        // batch the 4 independent gathers first -> MLP_p1 = 4
        float4 f0 = __ldg(&g_feat[s.x]);
        float4 f1 = __ldg(&g_feat[s.y]);
        float4 f2 = __ldg(&g_feat[s.z]);
        float4 f3 = __ldg(&g_feat[s.w]);
        red_v4(d.x, f0);
        red_v4(d.y, f1);
        red_v4(d.z, f2);
        red_v4(d.w, f3);
    } else if (i == e4 && rem) {
        int base = e4 * 4;
        for (int k = 0; k < rem; k++)
            red_v4(dst[base + k], __ldg(&g_feat[src[base + k]]));
    }
}

// ---------------- node phase: 1 node/thread (R2 version) --------------------
__global__ void node_kernel(const float* __restrict__ x_attr,
                            const float* __restrict__ label,
                            const float* __restrict__ W0, const float* __restrict__ b0,
                            const float* __restrict__ W1, const float* __restrict__ b1,
                            const float* __restrict__ W2, const float* __restrict__ b2,
                            const float* __restrict__ Wa, const float* __restrict__ ba,
                            float* __restrict__ out, int n) {
    __shared__ float sW0[3], sW1[9], sW2[6], sWa[27], sB[3], sBa[3];
    int t = threadIdx.x;
    if (t < 3)  { sW0[t] = W0[t]; sB[t] = b0[t] + b1[t] + b2[t]; sBa[t] = ba[t]; }
    if (t < 9)  sW1[t] = W1[t];
    if (t < 6)  sW2[t] = W2[t];
    if (t < 27) sWa[t] = Wa[t];
    __syncthreads();

    int i = blockIdx.x * blockDim.x + threadIdx.x;
    if (i >= n) return;

    float4 acc = g_accum[i];
    float inv = 1.0f / fmaxf(acc.w, 1.0f);
    float hg0 = acc.x * inv, hg1 = acc.y * inv, hg2 = acc.z * inv;

    float4 f4 = g_feat[i];
    float f0 = f4.x, f1 = f4.y, f2 = f4.z;
    float x0 = x_attr[2 * i], x1 = x_attr[2 * i + 1];
    float lb = label[i];

    float a[3];
#pragma unroll
    for (int j = 0; j < 3; j++) {
        float v = lb * sW0[j]
                + hg0 * sW1[j] + hg1 * sW1[3 + j] + hg2 * sW1[6 + j]
                + x0 * sW2[j] + x1 * sW2[3 + j]
                + sB[j];
        a[j] = fmaxf(v, 0.f);
    }

#pragma unroll
    for (int j = 0; j < 3; j++) {
        float v = a[0] * sWa[j] + a[1] * sWa[3 + j] + a[2] * sWa[6 + j]
                + hg0 * sWa[9 + j] + hg1 * sWa[12 + j] + hg2 * sWa[15 + j]
                + f0 * sWa[18 + j] + f1 * sWa[21 + j] + f2 * sWa[24 + j]
                + sBa[j];
        out[3 * i + j] = fmaxf(v, 0.f);
    }
}

extern "C" void kernel_launch(void* const* d_in, const int* in_sizes, int n_in,
                              void* d_out, int out_size) {
    const float* feature = (const float*)d_in[0];
    const float* x_attr  = (const float*)d_in[1];
    const float* label   = (const float*)d_in[2];
    const float* W0 = (const float*)d_in[3];
    const float* b0 = (const float*)d_in[4];
    const float* W1 = (const float*)d_in[5];
    const float* b1 = (const float*)d_in[6];
    const float* W2 = (const float*)d_in[7];
    const float* b2 = (const float*)d_in[8];
    const float* Wa = (const float*)d_in[9];
    const float* ba = (const float*)d_in[10];
    const int*   src = (const int*)d_in[11];
    const int*   dst = (const int*)d_in[12];
    float* out = (float*)d_out;

    int N = in_sizes[0] / 3;
    int E = in_sizes[11];
    int e4 = E / 4;
    int rem = E % 4;

    const int TB = 256;
    prep_kernel<<<(N + TB - 1) / TB, TB>>>(feature, N);

    int edge_thr = e4 + (rem ? 1 : 0);
    edge_kernel<<<(edge_thr + TB - 1) / TB, TB>>>(src, dst, e4, rem);

    node_kernel<<<(N + TB - 1) / TB, TB>>>(x_attr, label,
                                           W0, b0, W1, b1, W2, b2, Wa, ba,
                                           out, N);
}